// round 2
// baseline (speedup 1.0000x reference)
#include <cuda_runtime.h>
#include <math.h>

#define Nn   8
#define Cc   64
#define Hh   128
#define Ww   128
#define HW   (Hh * Ww)          // 16384
#define TOT  (Nn * Cc * HW)     // 8388608
#define CCK  8                  // ci chunk size
#define TILE 16

// Allocation-free scratch (device globals allowed; cudaMalloc is not).
__device__ float  g_y[TOT];
__device__ double g_sum[Cc];
__device__ double g_sq[Cc];
__device__ float  g_a[Cc];
__device__ float  g_b[Cc];

// ---------------------------------------------------------------------------
// Pass 0: zero the channel accumulators
// ---------------------------------------------------------------------------
__global__ void k0_zero() {
    int t = threadIdx.x;
    if (t < Cc) { g_sum[t] = 0.0; g_sq[t] = 0.0; }
}

// ---------------------------------------------------------------------------
// Pass 1: adder2d (-sum |patch - w|) + residual, write y, accumulate per-channel
//         sum / sumsq (double) for BN batch statistics.
// Grid: (8 tiles x, 8 tiles y, 8 images), 256 threads, 1 output pixel/thread,
// all 64 output channels accumulated in registers.
// ---------------------------------------------------------------------------
__global__ __launch_bounds__(256, 2)
void k1_adder(const float* __restrict__ x, const float* __restrict__ wgt) {
    __shared__ float  xs[CCK][TILE + 2][TILE + 2];
    __shared__ float  ws[CCK][Cc][9];
    __shared__ double ssum[Cc];
    __shared__ double ssq[Cc];

    const int n   = blockIdx.z;
    const int ty0 = blockIdx.y * TILE;
    const int tx0 = blockIdx.x * TILE;
    const int tid = threadIdx.x;
    const int ty  = tid >> 4;
    const int tx  = tid & 15;

    float acc[Cc];
#pragma unroll
    for (int i = 0; i < Cc; i++) acc[i] = 0.0f;

    for (int cb = 0; cb < Cc; cb += CCK) {
        __syncthreads();
        // ---- stage x halo tile: xs[ci][r][c] = x[n][cb+ci][ty0-1+r][tx0-1+c]
        for (int i = tid; i < CCK * (TILE + 2) * (TILE + 2); i += 256) {
            int ci = i / ((TILE + 2) * (TILE + 2));
            int r  = (i / (TILE + 2)) % (TILE + 2);
            int c  = i % (TILE + 2);
            int gh = ty0 - 1 + r;
            int gw = tx0 - 1 + c;
            float v = 0.0f;
            if ((unsigned)gh < (unsigned)Hh && (unsigned)gw < (unsigned)Ww)
                v = x[((n * Cc + cb + ci) * Hh + gh) * Ww + gw];
            xs[ci][r][c] = v;
        }
        // ---- stage weights: ws[ci][co][k] = wgt[(co*Cc + cb+ci)*9 + k]
        for (int i = tid; i < CCK * Cc * 9; i += 256) {
            int ci  = i / (Cc * 9);
            int rem = i % (Cc * 9);
            int co  = rem / 9;
            int k   = rem % 9;
            ws[ci][co][k] = wgt[(co * Cc + cb + ci) * 9 + k];
        }
        __syncthreads();

        for (int ci = 0; ci < CCK; ci++) {
            float p[9];
#pragma unroll
            for (int kh = 0; kh < 3; kh++)
#pragma unroll
                for (int kw = 0; kw < 3; kw++)
                    p[kh * 3 + kw] = xs[ci][ty + kh][tx + kw];

            const float* wp = &ws[ci][0][0];
#pragma unroll
            for (int co = 0; co < Cc; co++) {   // FULL unroll: acc[] stays in regs
                float s = acc[co];
#pragma unroll
                for (int k = 0; k < 9; k++)
                    s -= fabsf(p[k] - wp[co * 9 + k]);
                acc[co] = s;
            }
        }
    }

    // ---- epilogue: residual, store y, per-channel stats
    __syncthreads();
    if (tid < Cc) { ssum[tid] = 0.0; ssq[tid] = 0.0; }
    __syncthreads();

    const int h    = ty0 + ty;
    const int w    = tx0 + tx;
    const int base = n * Cc * HW + h * Ww + w;
    const float* xr = x + base;
    float*       yw = g_y + base;
    const int lane  = tid & 31;

#pragma unroll
    for (int co = 0; co < Cc; co++) {          // FULL unroll: constant acc index
        float y = acc[co] + xr[co * HW];
        yw[co * HW] = y;
        float s = y;
        float q = y * y;
#pragma unroll
        for (int off = 16; off; off >>= 1) {
            s += __shfl_xor_sync(0xffffffffu, s, off);
            q += __shfl_xor_sync(0xffffffffu, q, off);
        }
        if (lane == 0) {
            atomicAdd(&ssum[co], (double)s);
            atomicAdd(&ssq[co], (double)q);
        }
    }
    __syncthreads();
    if (tid < Cc) {
        atomicAdd(&g_sum[tid], ssum[tid]);
        atomicAdd(&g_sq[tid],  ssq[tid]);
    }
}

// ---------------------------------------------------------------------------
// Pass 2: fold BN into per-channel affine (a, b)
// ---------------------------------------------------------------------------
__global__ void k2_stats(const float* __restrict__ gamma,
                         const float* __restrict__ beta) {
    int c = threadIdx.x;
    if (c < Cc) {
        const double cnt = (double)(Nn * HW);
        double mean = g_sum[c] / cnt;
        double var  = g_sq[c] / cnt - mean * mean;
        float inv   = (float)(1.0 / sqrt(var + 1e-5));
        float a     = gamma[c] * inv;
        g_a[c] = a;
        g_b[c] = beta[c] - (float)mean * a;
    }
}

// ---------------------------------------------------------------------------
// Pass 3: normalize + PowerActivation, float4-vectorized
// ---------------------------------------------------------------------------
__global__ void k3_out(float* __restrict__ out, const float* __restrict__ alpha) {
    const float al = *alpha;
    int i4 = blockIdx.x * blockDim.x + threadIdx.x;     // index in float4 units
    if (i4 < TOT / 4) {
        int i = i4 * 4;
        int c = (i >> 14) & 63;                          // HW = 16384 = 2^14
        float a = g_a[c], b = g_b[c];
        float4 yv = *reinterpret_cast<const float4*>(&g_y[i]);
        float t0 = yv.x * a + b;
        float t1 = yv.y * a + b;
        float t2 = yv.z * a + b;
        float t3 = yv.w * a + b;
        float r0 = powf(fabsf(t0) + 1e-12f, al);
        float r1 = powf(fabsf(t1) + 1e-12f, al);
        float r2 = powf(fabsf(t2) + 1e-12f, al);
        float r3 = powf(fabsf(t3) + 1e-12f, al);
        float4 ov;
        ov.x = (t0 > 0.0f) ? r0 : ((t0 < 0.0f) ? -r0 : 0.0f);
        ov.y = (t1 > 0.0f) ? r1 : ((t1 < 0.0f) ? -r1 : 0.0f);
        ov.z = (t2 > 0.0f) ? r2 : ((t2 < 0.0f) ? -r2 : 0.0f);
        ov.w = (t3 > 0.0f) ? r3 : ((t3 < 0.0f) ? -r3 : 0.0f);
        *reinterpret_cast<float4*>(&out[i]) = ov;
    }
}

// ---------------------------------------------------------------------------
extern "C" void kernel_launch(void* const* d_in, const int* in_sizes, int n_in,
                              void* d_out, int out_size) {
    const float* x     = (const float*)d_in[0];   // [8,64,128,128]
    const float* wgt   = (const float*)d_in[1];   // [64,64,3,3]
    const float* gamma = (const float*)d_in[2];   // [64]
    const float* beta  = (const float*)d_in[3];   // [64]
    const float* alpha = (const float*)d_in[4];   // [1]
    float* out = (float*)d_out;

    k0_zero<<<1, 64>>>();
    dim3 grid(Ww / TILE, Hh / TILE, Nn);          // 8 x 8 x 8
    k1_adder<<<grid, 256>>>(x, wgt);
    k2_stats<<<1, 64>>>(gamma, beta);
    k3_out<<<(TOT / 4 + 255) / 256, 256>>>(out, alpha);
}